// round 11
// baseline (speedup 1.0000x reference)
#include <cuda_runtime.h>
#include <math.h>

#define SLEN   2048
#define HEADS  32
#define DHEAD  128
#define TQ     128
#define TK     64
#define NT     256
#define WPITCH 132

// ---------------- shared memory layout ----------------
// Qs: [128 rows][32 float4] LINEAR (loads are ty-broadcast -> no conflicts;
//     stores are lane-consecutive -> no conflicts). No swizzle needed.
// Ks: two buffers [64 rows][32 float4], XOR swizzle phys_d4 = d4 ^ (row & 7).
//     Ks[1] doubles as the V tile in pass 2.
// Ws: [64 k-cols][132 floats] (pitch 132: 16B-aligned float4 rows)
struct __align__(16) Smem {
    float4 Qs[TQ * 32];        // 64 KB
    float4 Ks[2][TK * 32];     // 2 x 32 KB
    float  Ws[TK * WPITCH];    // 33.8 KB
};

// f32 exp(x) for |x| <= 0.4 (~0.5 ulp), pass 1 only (feeds fp64 sum).
__device__ __forceinline__ float expP(float x)
{
    float p = 1.0f / 5040.0f;
    p = fmaf(p, x, 1.0f / 720.0f);
    p = fmaf(p, x, 1.0f / 120.0f);
    p = fmaf(p, x, 1.0f / 24.0f);
    p = fmaf(p, x, 1.0f / 6.0f);
    p = fmaf(p, x, 0.5f);
    p = fmaf(p, x, 1.0f);
    return fmaf(p, x, 1.0f);
}

// Correctly-rounded f32 exp for t in [-0.4, 0]: degree-10 Taylor in double,
// single rounding to f32 (bit-matches correctly-rounded libm expf). Pass 2.
__device__ __forceinline__ float expCR(float t)
{
    const double x = (double)t;
    double p = 1.0 / 3628800.0;
    p = fma(p, x, 1.0 / 362880.0);
    p = fma(p, x, 1.0 / 40320.0);
    p = fma(p, x, 1.0 / 5040.0);
    p = fma(p, x, 1.0 / 720.0);
    p = fma(p, x, 1.0 / 120.0);
    p = fma(p, x, 1.0 / 24.0);
    p = fma(p, x, 1.0 / 6.0);
    p = fma(p, x, 0.5);
    p = fma(p, x, 1.0);
    p = fma(p, x, 1.0);
    return (float)p;
}

// 128x64x128 fp32 GEMM, 8x4 micro-tile:
//   s[i][u] = dot(Q row 8*ty+i, K row tx+16*u)
// Single-accumulator fmaf chain, ascending d (x,y,z,w within float4) ==
// Eigen gebp order. Shared by both passes -> bit-identical scores.
__device__ __forceinline__ void gemm_qk(const float4* __restrict__ Qs,
                                        const float4* __restrict__ Ks,
                                        int tx, int ty, float s[8][4])
{
    #pragma unroll
    for (int i = 0; i < 8; ++i)
        #pragma unroll
        for (int u = 0; u < 4; ++u)
            s[i][u] = 0.0f;

    const int xk = tx & 7;
    #pragma unroll 4
    for (int d4 = 0; d4 < 32; ++d4) {
        float4 q4[8], k4[4];
        #pragma unroll
        for (int i = 0; i < 8; ++i)
            q4[i] = Qs[(8 * ty + i) * 32 + d4];           // broadcast, linear
        const int kd = d4 ^ xk;                            // loop-invariant xor
        #pragma unroll
        for (int u = 0; u < 4; ++u)
            k4[u] = Ks[(tx + 16 * u) * 32 + kd];
        #pragma unroll
        for (int i = 0; i < 8; ++i)
            #pragma unroll
            for (int u = 0; u < 4; ++u) {
                s[i][u] = fmaf(q4[i].x, k4[u].x, s[i][u]);
                s[i][u] = fmaf(q4[i].y, k4[u].y, s[i][u]);
                s[i][u] = fmaf(q4[i].z, k4[u].z, s[i][u]);
                s[i][u] = fmaf(q4[i].w, k4[u].w, s[i][u]);
            }
    }
}

// v = s*norm + am (exact ref op order), dead = causal mask. Identical in
// both passes.
__device__ __forceinline__ void scale_mask(float s[8][4], float v[8][4], int dead[8][4],
                                           const float* __restrict__ am,
                                           int kb, int tx, int ty, int q0, bool diag,
                                           float norm)
{
    float amv[4];
    #pragma unroll
    for (int u = 0; u < 4; ++u) amv[u] = __ldg(&am[kb + tx + 16 * u]);

    #pragma unroll
    for (int i = 0; i < 8; ++i) {
        const int qr = q0 + 8 * ty + i;
        #pragma unroll
        for (int u = 0; u < 4; ++u) {
            const int kc = kb + tx + 16 * u;
            v[i][u] = __fadd_rn(__fmul_rn(s[i][u], norm), amv[u]);
            dead[i][u] = diag && (kc > qr);
        }
    }
}

__global__ void __launch_bounds__(NT)
attn_kernel(const float* __restrict__ Q, const float* __restrict__ K,
            const float* __restrict__ V, const float* __restrict__ AM,
            float* __restrict__ O)
{
    extern __shared__ float4 smem_raw[];
    Smem& sm = *reinterpret_cast<Smem*>(smem_raw);

    const int tid = threadIdx.x;
    const int tx  = tid & 15;        // 16 column-group lanes
    const int ty  = tid >> 4;        // 16 row groups of 8
    const int qt  = (int)gridDim.x - 1 - (int)blockIdx.x;  // heavy tiles first
    const int bh  = (int)blockIdx.y;
    const int b   = bh >> 5;
    const int h   = bh & 31;
    const int q0  = qt * TQ;
    const int nkt = 2 * qt + 2;      // k-tiles (TK=64) covering rows < q0+128

    // norm exactly as numpy computes it, rounding at every f32 step.
    const float sq128 = (float)11.313708498984761;   // f32(np.sqrt(128))
    const float norm  = __fmul_rn(__fmul_rn(__fdiv_rn(1.0f, sq128), 0.1f), 0.1f);
    const float c1    = (float)((1.0 / 255.0) * (1.0 / 10.0));

    const size_t base = (size_t)bh * SLEN * DHEAD;
    const float* am   = AM + (size_t)b * SLEN;
    const float4* gq  = reinterpret_cast<const float4*>(Q + base) + (size_t)q0 * (DHEAD / 4);
    const float4* gk0 = reinterpret_cast<const float4*>(K + base);
    const float4* gv0 = reinterpret_cast<const float4*>(V + base);

    // ---- load Q tile, LINEAR layout (coalesced, conflict-free) ----
    #pragma unroll
    for (int j = 0; j < 16; ++j) {
        const int i = tid + NT * j;
        sm.Qs[i] = gq[i];
    }

    // Row stats: m = exact f32 max of masked scores; L = fp64 sum of exp(v).
    double L[8];
    float  m[8];
    #pragma unroll
    for (int i = 0; i < 8; ++i) { L[i] = 0.0; m[i] = -3.402823466e38f; }

    // ============ pass 1: row max m and unshifted denom L ============
    {
        float4 pk[8];
        #pragma unroll
        for (int j = 0; j < 8; ++j) pk[j] = gk0[tid + NT * j];
        #pragma unroll
        for (int j = 0; j < 8; ++j) {
            const int i = tid + NT * j;
            const int r = i >> 5, d4 = i & 31;
            sm.Ks[0][r * 32 + (d4 ^ (r & 7))] = pk[j];
        }
        __syncthreads();

        int p = 0;
        for (int kt = 0; kt < nkt; ++kt) {
            if (kt + 1 < nkt) {      // prefetch next K tile; LDG hidden by GEMM
                const float4* gk = gk0 + (size_t)(kt + 1) * TK * (DHEAD / 4);
                #pragma unroll
                for (int j = 0; j < 8; ++j) pk[j] = gk[tid + NT * j];
            }

            float s[8][4];
            gemm_qk(sm.Qs, sm.Ks[p], tx, ty, s);

            if (kt + 1 < nkt) {      // stage next tile in the OTHER buffer
                #pragma unroll
                for (int j = 0; j < 8; ++j) {
                    const int i = tid + NT * j;
                    const int r = i >> 5, d4 = i & 31;
                    sm.Ks[p ^ 1][r * 32 + (d4 ^ (r & 7))] = pk[j];
                }
            }

            float v[8][4]; int dead[8][4];
            scale_mask(s, v, dead, am, kt * TK, tx, ty, q0, kt >= 2 * qt, norm);

            #pragma unroll
            for (int i = 0; i < 8; ++i) {
                float e0 = dead[i][0] ? 0.0f : expP(v[i][0]);
                float e1 = dead[i][1] ? 0.0f : expP(v[i][1]);
                float e2 = dead[i][2] ? 0.0f : expP(v[i][2]);
                float e3 = dead[i][3] ? 0.0f : expP(v[i][3]);

                float t0 = dead[i][0] ? -3.402823466e38f : v[i][0];
                float t1 = dead[i][1] ? -3.402823466e38f : v[i][1];
                float t2 = dead[i][2] ? -3.402823466e38f : v[i][2];
                float t3 = dead[i][3] ? -3.402823466e38f : v[i][3];
                float t = fmaxf(fmaxf(t0, t1), fmaxf(t2, t3));
                #pragma unroll
                for (int msk = 1; msk < 16; msk <<= 1)
                    t = fmaxf(t, __shfl_xor_sync(0xffffffffu, t, msk));
                m[i] = fmaxf(m[i], t);

                double rs = ((double)e0 + (double)e1) + ((double)e2 + (double)e3);
                #pragma unroll
                for (int msk = 1; msk < 16; msk <<= 1)
                    rs += __shfl_xor_sync(0xffffffffu, rs, msk);
                L[i] += rs;
            }
            __syncthreads();         // one barrier per tile
            p ^= 1;
        }
    }

    // ---- l in f32 (value the ref divides by): l = L * exp(-m), near-exact ----
    float lf[8];
    int needp = 0;
    #pragma unroll
    for (int i = 0; i < 8; ++i) {
        lf[i] = (float)(L[i] * exp(-(double)m[i]));
        // skip test with EXACTLY the pass-2 weight arithmetic at e = 1
        // (argmax element has e = expCR(0) = 1); weights monotone in e.
        const float zmax = __fmul_rn(__fdiv_rn(1.0f, lf[i]), 255.0f);
        if (rintf(zmax) >= 1.0f) needp = 1;
    }
    const int need = __syncthreads_or(needp);

    if (!need) {
        // whole tile quantizes to zero — write zeros (out is poisoned)
        const float4 z = make_float4(0.f, 0.f, 0.f, 0.f);
        #pragma unroll
        for (int i = 0; i < 8; ++i) {
            const int row = q0 + 8 * ty + i;
            float4* p = reinterpret_cast<float4*>(
                O + ((size_t)b * SLEN + row) * (HEADS * DHEAD) + h * DHEAD + 8 * tx);
            p[0] = z; p[1] = z;
        }
        return;
    }

    // ============ pass 2: quantized weights + W @ V ============
    // fp32 accumulators, fmaf in STRICTLY ascending global k order
    // (Eigen-sequential emulation; zero weights add exactly 0).
    float acc[8][8];
    #pragma unroll
    for (int i = 0; i < 8; ++i)
        #pragma unroll
        for (int jj = 0; jj < 8; ++jj) acc[i][jj] = 0.0f;

    for (int kt = 0; kt < nkt; ++kt) {
        __syncthreads();   // previous iteration's Vs/Ws readers done
        {
            const float4* gk = gk0 + (size_t)kt * TK * (DHEAD / 4);
            const float4* gv = gv0 + (size_t)kt * TK * (DHEAD / 4);
            float4 t[8];
            #pragma unroll
            for (int j = 0; j < 8; ++j) t[j] = gk[tid + NT * j];
            #pragma unroll
            for (int j = 0; j < 8; ++j) {
                const int i = tid + NT * j;
                const int r = i >> 5, d4 = i & 31;
                sm.Ks[0][r * 32 + (d4 ^ (r & 7))] = t[j];
            }
            #pragma unroll
            for (int j = 0; j < 8; ++j) t[j] = gv[tid + NT * j];
            #pragma unroll
            for (int j = 0; j < 8; ++j) {
                const int i = tid + NT * j;
                const int r = i >> 5, d4 = i & 31;
                sm.Ks[1][r * 32 + (d4 ^ (r & 7))] = t[j];   // V tile
            }
        }
        __syncthreads();

        float s[8][4];
        gemm_qk(sm.Qs, sm.Ks[0], tx, ty, s);               // identical to pass 1
        float v[8][4]; int dead[8][4];
        scale_mask(s, v, dead, am, kt * TK, tx, ty, q0, kt >= 2 * qt, norm);

        // w = clip(rint(f32(f32(expCR(f32(v-m)) / l) * 255)), 0, 255)
        #pragma unroll
        for (int u = 0; u < 4; ++u) {
            const int c = tx + 16 * u;
            float w[8];
            #pragma unroll
            for (int i = 0; i < 8; ++i) {
                if (dead[i][u]) {
                    w[i] = 0.0f;
                } else {
                    const float t2 = __fadd_rn(v[i][u], -m[i]);
                    const float e  = expCR(t2);            // = 1.0f at argmax
                    const float z  = __fmul_rn(__fdiv_rn(e, lf[i]), 255.0f);
                    w[i] = fminf(rintf(z), 255.0f);
                }
            }
            *reinterpret_cast<float4*>(&sm.Ws[c * WPITCH + 8 * ty])
                = make_float4(w[0], w[1], w[2], w[3]);
            *reinterpret_cast<float4*>(&sm.Ws[c * WPITCH + 8 * ty + 4])
                = make_float4(w[4], w[5], w[6], w[7]);
        }
        __syncthreads();

        // acc[r][d] += W[r][c] * V[c][d], c ascending (global k ascending)
        #pragma unroll 4
        for (int c = 0; c < 64; ++c) {
            const float4 wa = *reinterpret_cast<const float4*>(&sm.Ws[c * WPITCH + 8 * ty]);
            const float4 wb = *reinterpret_cast<const float4*>(&sm.Ws[c * WPITCH + 8 * ty + 4]);
            const float4 v0 = sm.Ks[1][c * 32 + ((2 * tx)     ^ (c & 7))];
            const float4 v1 = sm.Ks[1][c * 32 + ((2 * tx + 1) ^ (c & 7))];
            const float wv[8] = { wa.x, wa.y, wa.z, wa.w, wb.x, wb.y, wb.z, wb.w };
            #pragma unroll
            for (int i = 0; i < 8; ++i) {
                acc[i][0] = fmaf(wv[i], v0.x, acc[i][0]);
                acc[i][1] = fmaf(wv[i], v0.y, acc[i][1]);
                acc[i][2] = fmaf(wv[i], v0.z, acc[i][2]);
                acc[i][3] = fmaf(wv[i], v0.w, acc[i][3]);
                acc[i][4] = fmaf(wv[i], v1.x, acc[i][4]);
                acc[i][5] = fmaf(wv[i], v1.y, acc[i][5]);
                acc[i][6] = fmaf(wv[i], v1.z, acc[i][6]);
                acc[i][7] = fmaf(wv[i], v1.w, acc[i][7]);
            }
        }
    }

    // ---- epilogue: exact ref op order on the emulated f32 einsum result ----
    #pragma unroll
    for (int i = 0; i < 8; ++i) {
        float o[8];
        #pragma unroll
        for (int jj = 0; jj < 8; ++jj) {
            float y = __fmul_rn(acc[i][jj], c1);   // out * f32(1/2550)
            y = __fmul_rn(y, 127.0f);              // * REQUANT
            y = rintf(y);                          // round half-to-even
            o[jj] = fminf(fmaxf(y, -128.0f), 127.0f);
        }
        const int row = q0 + 8 * ty + i;
        float4* p = reinterpret_cast<float4*>(
            O + ((size_t)b * SLEN + row) * (HEADS * DHEAD) + h * DHEAD + 8 * tx);
        p[0] = make_float4(o[0], o[1], o[2], o[3]);
        p[1] = make_float4(o[4], o[5], o[6], o[7]);
    }
}

extern "C" void kernel_launch(void* const* d_in, const int* in_sizes, int n_in,
                              void* d_out, int out_size)
{
    (void)in_sizes; (void)n_in; (void)out_size;
    const float* q  = (const float*)d_in[0];
    const float* k  = (const float*)d_in[1];
    const float* v  = (const float*)d_in[2];
    const float* am = (const float*)d_in[3];
    float* out = (float*)d_out;

    const int smem = (int)sizeof(Smem);   // 164864 B
    cudaFuncSetAttribute(attn_kernel, cudaFuncAttributeMaxDynamicSharedMemorySize, smem);

    dim3 grid(SLEN / TQ, 2 * HEADS);      // (16 q-tiles, 64 batch*head)
    attn_kernel<<<grid, NT, smem>>>(q, k, v, am, out);
}

// round 12
// speedup vs baseline: 1.5110x; 1.5110x over previous
#include <cuda_runtime.h>
#include <math.h>

#define SLEN   2048
#define HEADS  32
#define DHEAD  128
#define TQ     64
#define TK     64
#define NT     256

// ---------------- shared memory layout (113 KB -> 2 CTAs/SM) ----------------
// Qs:     [64 rows][32 float4], XOR swizzle phys_d4 = d4 ^ (row & 7)
// KA/KB:  [64 rows][32 float4] swizzled. Pass 1: K ping-pong buffers.
//         Pass 2: KA = K tile, KB = V tile.
// Ws:     [64 cols][68 floats] (pitch 68 keeps float4 reads aligned)
struct __align__(16) Smem {
    float4 Qs[TQ * 32];
    float4 KA[TK * 32];
    float4 KB[TK * 32];
    float  Ws[TK * 68];
};

// f32 exp(x) for |x| <= 0.4 (~0.5 ulp), pass 1 only (feeds fp64 sum).
__device__ __forceinline__ float expP(float x)
{
    float p = 1.0f / 5040.0f;
    p = fmaf(p, x, 1.0f / 720.0f);
    p = fmaf(p, x, 1.0f / 120.0f);
    p = fmaf(p, x, 1.0f / 24.0f);
    p = fmaf(p, x, 1.0f / 6.0f);
    p = fmaf(p, x, 0.5f);
    p = fmaf(p, x, 1.0f);
    return fmaf(p, x, 1.0f);
}

// Correctly-rounded f32 exp for t in [-0.4, 0]: degree-10 Taylor in double,
// single rounding to f32 (bit-matches correctly-rounded libm expf). Pass 2.
__device__ __forceinline__ float expCR(float t)
{
    const double x = (double)t;
    double p = 1.0 / 3628800.0;
    p = fma(p, x, 1.0 / 362880.0);
    p = fma(p, x, 1.0 / 40320.0);
    p = fma(p, x, 1.0 / 5040.0);
    p = fma(p, x, 1.0 / 720.0);
    p = fma(p, x, 1.0 / 120.0);
    p = fma(p, x, 1.0 / 24.0);
    p = fma(p, x, 1.0 / 6.0);
    p = fma(p, x, 0.5);
    p = fma(p, x, 1.0);
    p = fma(p, x, 1.0);
    return (float)p;
}

// 64x64x128 fp32 GEMM: s[i][u] = dot(Q row 4*ty+i, K row tx+16*u)
// Single-accumulator fmaf chain, ascending d == Eigen gebp order; shared
// (inlined) by pass 1 and pass 2 so both produce bit-identical scores.
__device__ __forceinline__ void gemm_qk(const float4* __restrict__ Qs,
                                        const float4* __restrict__ Ks,
                                        int tx, int ty, float s[4][4])
{
    #pragma unroll
    for (int i = 0; i < 4; ++i)
        #pragma unroll
        for (int u = 0; u < 4; ++u)
            s[i][u] = 0.0f;

    #pragma unroll 8
    for (int d4 = 0; d4 < 32; ++d4) {
        float4 q4[4], k4[4];
        #pragma unroll
        for (int i = 0; i < 4; ++i) {
            const int r = 4 * ty + i;
            q4[i] = Qs[r * 32 + (d4 ^ (r & 7))];
        }
        #pragma unroll
        for (int u = 0; u < 4; ++u) {
            const int c = tx + 16 * u;
            k4[u] = Ks[c * 32 + (d4 ^ (c & 7))];
        }
        #pragma unroll
        for (int i = 0; i < 4; ++i)
            #pragma unroll
            for (int u = 0; u < 4; ++u) {
                s[i][u] = fmaf(q4[i].x, k4[u].x, s[i][u]);
                s[i][u] = fmaf(q4[i].y, k4[u].y, s[i][u]);
                s[i][u] = fmaf(q4[i].z, k4[u].z, s[i][u]);
                s[i][u] = fmaf(q4[i].w, k4[u].w, s[i][u]);
            }
    }
}

// v = s*norm + am (exact ref op order), dead = causal mask.
// Deterministic, used IDENTICALLY in both passes.
__device__ __forceinline__ void scale_mask(float s[4][4], float v[4][4], int dead[4][4],
                                           const float* __restrict__ am,
                                           int kb, int tx, int ty, int q0, bool diag,
                                           float norm)
{
    float amv[4];
    #pragma unroll
    for (int u = 0; u < 4; ++u) amv[u] = __ldg(&am[kb + tx + 16 * u]);

    #pragma unroll
    for (int i = 0; i < 4; ++i) {
        const int qr = q0 + 4 * ty + i;
        #pragma unroll
        for (int u = 0; u < 4; ++u) {
            const int kc = kb + tx + 16 * u;
            v[i][u] = __fadd_rn(__fmul_rn(s[i][u], norm), amv[u]);
            dead[i][u] = diag && (kc > qr);
        }
    }
}

__global__ void __launch_bounds__(NT)
attn_kernel(const float* __restrict__ Q, const float* __restrict__ K,
            const float* __restrict__ V, const float* __restrict__ AM,
            float* __restrict__ O)
{
    extern __shared__ float4 smem_raw[];
    Smem& sm = *reinterpret_cast<Smem*>(smem_raw);

    const int tid = threadIdx.x;
    const int tx  = tid & 15;        // 16 column-group lanes
    const int ty  = tid >> 4;        // 16 row groups of 4
    const int qt  = (int)gridDim.x - 1 - (int)blockIdx.x;  // heavy tiles first
    const int bh  = (int)blockIdx.y;
    const int b   = bh >> 5;
    const int h   = bh & 31;
    const int q0  = qt * TQ;

    // norm exactly as numpy computes it, rounding at every f32 step.
    const float sq128 = (float)11.313708498984761;   // f32(np.sqrt(128))
    const float norm  = __fmul_rn(__fmul_rn(__fdiv_rn(1.0f, sq128), 0.1f), 0.1f);
    const float c1    = (float)((1.0 / 255.0) * (1.0 / 10.0));

    const size_t base = (size_t)bh * SLEN * DHEAD;
    const float* am   = AM + (size_t)b * SLEN;
    const float4* gq  = reinterpret_cast<const float4*>(Q + base) + (size_t)q0 * (DHEAD / 4);
    const float4* gk0 = reinterpret_cast<const float4*>(K + base);
    const float4* gv0 = reinterpret_cast<const float4*>(V + base);

    // ---- load Q tile (coalesced, XOR-swizzled store) ----
    #pragma unroll
    for (int j = 0; j < 8; ++j) {
        const int i = tid + NT * j;
        const int r = i >> 5, d4 = i & 31;
        sm.Qs[r * 32 + (d4 ^ (r & 7))] = gq[i];
    }

    // Per-thread partial stats (reduced across lanes once, after pass 1):
    //   mloc = running f32 max of live scores (exact, order-independent)
    //   Lp   = running fp64 sum of exp(v) (reassociation error ~1e-16 rel)
    double Lp[4];
    float  mloc[4];
    #pragma unroll
    for (int i = 0; i < 4; ++i) { Lp[i] = 0.0; mloc[i] = -3.402823466e38f; }

    // ========== pass 1: K ping-pong (KA/KB), ONE barrier per tile ==========
    {
        float4* const buf[2] = { sm.KA, sm.KB };

        float4 pk[8];
        #pragma unroll
        for (int j = 0; j < 8; ++j) pk[j] = gk0[tid + NT * j];
        #pragma unroll
        for (int j = 0; j < 8; ++j) {
            const int i = tid + NT * j;
            const int r = i >> 5, d4 = i & 31;
            sm.KA[r * 32 + (d4 ^ (r & 7))] = pk[j];
        }
        __syncthreads();

        int p = 0;
        for (int kt = 0; kt <= qt; ++kt) {
            if (kt < qt) {       // prefetch next K tile (LDG hidden by GEMM)
                const float4* gk = gk0 + (size_t)(kt + 1) * TK * (DHEAD / 4);
                #pragma unroll
                for (int j = 0; j < 8; ++j) pk[j] = gk[tid + NT * j];
            }

            float s[4][4];
            gemm_qk(sm.Qs, buf[p], tx, ty, s);

            if (kt < qt) {       // stage next tile in the OTHER buffer (no race)
                float4* dst = buf[p ^ 1];
                #pragma unroll
                for (int j = 0; j < 8; ++j) {
                    const int i = tid + NT * j;
                    const int r = i >> 5, d4 = i & 31;
                    dst[r * 32 + (d4 ^ (r & 7))] = pk[j];
                }
            }

            float v[4][4]; int dead[4][4];
            scale_mask(s, v, dead, am, kt * TK, tx, ty, q0, kt == qt, norm);

            #pragma unroll
            for (int i = 0; i < 4; ++i) {
                const float e0 = dead[i][0] ? 0.0f : expP(v[i][0]);
                const float e1 = dead[i][1] ? 0.0f : expP(v[i][1]);
                const float e2 = dead[i][2] ? 0.0f : expP(v[i][2]);
                const float e3 = dead[i][3] ? 0.0f : expP(v[i][3]);
                Lp[i] += (double)((e0 + e1) + (e2 + e3));   // 1 DADD/row/tile

                const float t0 = dead[i][0] ? -3.402823466e38f : v[i][0];
                const float t1 = dead[i][1] ? -3.402823466e38f : v[i][1];
                const float t2 = dead[i][2] ? -3.402823466e38f : v[i][2];
                const float t3 = dead[i][3] ? -3.402823466e38f : v[i][3];
                mloc[i] = fmaxf(mloc[i], fmaxf(fmaxf(t0, t1), fmaxf(t2, t3)));
            }

            __syncthreads();     // publishes buf[p^1] for the next iteration
            p ^= 1;
        }
    }

    // ---- one-time cross-lane reduction (16 tx lanes within each half-warp) ----
    double L[4];
    float  m[4];
    #pragma unroll
    for (int i = 0; i < 4; ++i) {
        float t = mloc[i];
        #pragma unroll
        for (int msk = 1; msk < 16; msk <<= 1)
            t = fmaxf(t, __shfl_xor_sync(0xffffffffu, t, msk));
        m[i] = t;                                   // exact f32 row max

        double rs = Lp[i];
        #pragma unroll
        for (int msk = 1; msk < 16; msk <<= 1)
            rs += __shfl_xor_sync(0xffffffffu, rs, msk);
        L[i] = rs;
    }

    // ---- l in f32 (value the ref divides by): l = L * exp(-m), near-exact ----
    float lf[4];
    int needp = 0;
    #pragma unroll
    for (int i = 0; i < 4; ++i) {
        lf[i] = (float)(L[i] * exp(-(double)m[i]));
        // skip test with EXACTLY the pass-2 weight arithmetic at e = 1
        // (argmax element has e = expCR(0) = 1); weights monotone in e.
        const float zmax = __fmul_rn(__fdiv_rn(1.0f, lf[i]), 255.0f);
        if (rintf(zmax) >= 1.0f) needp = 1;
    }
    const int need = __syncthreads_or(needp);

    if (!need) {
        // whole tile quantizes to zero — write zeros (out is poisoned)
        const float4 z = make_float4(0.f, 0.f, 0.f, 0.f);
        #pragma unroll
        for (int i = 0; i < 4; ++i) {
            const int row = q0 + 4 * ty + i;
            float4* p = reinterpret_cast<float4*>(
                O + ((size_t)b * SLEN + row) * (HEADS * DHEAD) + h * DHEAD + 8 * tx);
            p[0] = z; p[1] = z;
        }
        return;
    }

    // ================= pass 2: quantized weights + W @ V =================
    // fp32 accumulators, fmaf in STRICTLY ascending global k order
    // (Eigen-sequential emulation; zero weights add exactly 0).
    float acc[4][8];
    #pragma unroll
    for (int i = 0; i < 4; ++i)
        #pragma unroll
        for (int jj = 0; jj < 8; ++jj) acc[i][jj] = 0.0f;

    for (int kt = 0; kt <= qt; ++kt) {
        __syncthreads();   // previous iteration's KB/Ws readers done
        {
            const float4* gk = gk0 + (size_t)kt * TK * (DHEAD / 4);
            const float4* gv = gv0 + (size_t)kt * TK * (DHEAD / 4);
            #pragma unroll
            for (int j = 0; j < 8; ++j) {
                const int i = tid + NT * j;
                const int r = i >> 5, d4 = i & 31;
                const int idx = r * 32 + (d4 ^ (r & 7));
                sm.KA[idx] = gk[i];
                sm.KB[idx] = gv[i];    // V tile
            }
        }
        __syncthreads();

        float s[4][4];
        gemm_qk(sm.Qs, sm.KA, tx, ty, s);                  // identical to pass 1
        float v[4][4]; int dead[4][4];
        scale_mask(s, v, dead, am, kt * TK, tx, ty, q0, kt == qt, norm);

        // w = clip(rint(f32(f32(expCR(f32(v-m)) / l) * 255)), 0, 255)
        #pragma unroll
        for (int u = 0; u < 4; ++u) {
            const int c = tx + 16 * u;
            #pragma unroll
            for (int i = 0; i < 4; ++i) {
                float w;
                if (dead[i][u]) {
                    w = 0.0f;
                } else {
                    const float t2 = __fadd_rn(v[i][u], -m[i]);  // f32 (s - max)
                    const float e  = expCR(t2);                  // = 1.0f at argmax
                    const float z  = __fmul_rn(__fdiv_rn(e, lf[i]), 255.0f);
                    w = fminf(rintf(z), 255.0f);
                }
                sm.Ws[c * 68 + 4 * ty + i] = w;
            }
        }
        __syncthreads();

        // acc[r][d] += W[r][c] * V[c][d], c ascending (global k ascending)
        #pragma unroll 8
        for (int c = 0; c < 64; ++c) {
            const float4 w4 = *reinterpret_cast<const float4*>(&sm.Ws[c * 68 + 4 * ty]);
            const float4 v0 = sm.KB[c * 32 + ((2 * tx)     ^ (c & 7))];
            const float4 v1 = sm.KB[c * 32 + ((2 * tx + 1) ^ (c & 7))];
            const float wv[4] = { w4.x, w4.y, w4.z, w4.w };
            #pragma unroll
            for (int i = 0; i < 4; ++i) {
                acc[i][0] = fmaf(wv[i], v0.x, acc[i][0]);
                acc[i][1] = fmaf(wv[i], v0.y, acc[i][1]);
                acc[i][2] = fmaf(wv[i], v0.z, acc[i][2]);
                acc[i][3] = fmaf(wv[i], v0.w, acc[i][3]);
                acc[i][4] = fmaf(wv[i], v1.x, acc[i][4]);
                acc[i][5] = fmaf(wv[i], v1.y, acc[i][5]);
                acc[i][6] = fmaf(wv[i], v1.z, acc[i][6]);
                acc[i][7] = fmaf(wv[i], v1.w, acc[i][7]);
            }
        }
    }

    // ---- epilogue: exact ref op order on the emulated f32 einsum result ----
    #pragma unroll
    for (int i = 0; i < 4; ++i) {
        float o[8];
        #pragma unroll
        for (int jj = 0; jj < 8; ++jj) {
            float y = __fmul_rn(acc[i][jj], c1);   // out * f32(1/2550)
            y = __fmul_rn(y, 127.0f);              // * REQUANT
            y = rintf(y);                          // round half-to-even
            o[jj] = fminf(fmaxf(y, -128.0f), 127.0f);
        }
        const int row = q0 + 4 * ty + i;
        float4* p = reinterpret_cast<float4*>(
            O + ((size_t)b * SLEN + row) * (HEADS * DHEAD) + h * DHEAD + 8 * tx);
        p[0] = make_float4(o[0], o[1], o[2], o[3]);
        p[1] = make_float4(o[4], o[5], o[6], o[7]);
    }
}

extern "C" void kernel_launch(void* const* d_in, const int* in_sizes, int n_in,
                              void* d_out, int out_size)
{
    (void)in_sizes; (void)n_in; (void)out_size;
    const float* q  = (const float*)d_in[0];
    const float* k  = (const float*)d_in[1];
    const float* v  = (const float*)d_in[2];
    const float* am = (const float*)d_in[3];
    float* out = (float*)d_out;

    const int smem = (int)sizeof(Smem);   // 115712 B -> 2 CTAs/SM
    cudaFuncSetAttribute(attn_kernel, cudaFuncAttributeMaxDynamicSharedMemorySize, smem);

    dim3 grid(SLEN / TQ, 2 * HEADS);      // (32 q-tiles, 64 batch*head)
    attn_kernel<<<grid, NT, smem>>>(q, k, v, am, out);
}

// round 13
// speedup vs baseline: 1.6574x; 1.0969x over previous
#include <cuda_runtime.h>
#include <math.h>

#define SLEN   2048
#define HEADS  32
#define DHEAD  128
#define TQ     64
#define TK     64
#define NT     256
#define QPITCH 33   // odd float4 pitch: rows r and r+4 land on different 16B banks

// ---------------- shared memory layout (101.5 KB -> 2 CTAs/SM) ----------------
// Qs: [64 rows][pitch 33 float4] LINEAR (loads are ty-broadcast, stores are
//     lane-linear; odd pitch avoids the 2-way conflict between the two per-warp
//     row addresses). Zero address ALU on Q loads.
// KA/KB: [64 rows][32 float4], XOR swizzle phys_d4 = d4 ^ (row & 7).
//        Pass 1: K ping-pong. Pass 2: KA = K tile, KB = V tile.
// Wu: packed u8 weights [64 k-cols][pitch 18 words], word c*18+ty holds rows
//     4ty..4ty+3 (conflict-free store: (18c+ty) mod 32 distinct per warp).
struct __align__(16) Smem {
    float4   Qs[TQ * QPITCH];   // 33792 B
    float4   KA[TK * 32];       // 32768 B
    float4   KB[TK * 32];       // 32768 B
    unsigned Wu[TK * 18];       //  4608 B
};

// f32 exp(x) for |x| <= 0.4 (~0.5 ulp), pass 1 only (feeds fp64 sum).
__device__ __forceinline__ float expP(float x)
{
    float p = 1.0f / 5040.0f;
    p = fmaf(p, x, 1.0f / 720.0f);
    p = fmaf(p, x, 1.0f / 120.0f);
    p = fmaf(p, x, 1.0f / 24.0f);
    p = fmaf(p, x, 1.0f / 6.0f);
    p = fmaf(p, x, 0.5f);
    p = fmaf(p, x, 1.0f);
    return fmaf(p, x, 1.0f);
}

// Correctly-rounded f32 exp for t in [-0.4, 0]: degree-10 Taylor in double,
// single rounding to f32 (bit-matches correctly-rounded libm expf). Pass 2.
__device__ __forceinline__ float expCR(float t)
{
    const double x = (double)t;
    double p = 1.0 / 3628800.0;
    p = fma(p, x, 1.0 / 362880.0);
    p = fma(p, x, 1.0 / 40320.0);
    p = fma(p, x, 1.0 / 5040.0);
    p = fma(p, x, 1.0 / 720.0);
    p = fma(p, x, 1.0 / 120.0);
    p = fma(p, x, 1.0 / 24.0);
    p = fma(p, x, 1.0 / 6.0);
    p = fma(p, x, 0.5);
    p = fma(p, x, 1.0);
    p = fma(p, x, 1.0);
    return (float)p;
}

// 64x64x128 fp32 GEMM: s[i][u] = dot(Q row 4*ty+i, K row tx+16*u)
// Single-accumulator fmaf chain, ascending d == Eigen gebp order; shared
// (inlined) by pass 1 and pass 2 so both produce bit-identical scores.
__device__ __forceinline__ void gemm_qk(const float4* __restrict__ Qs,
                                        const float4* __restrict__ Ks,
                                        int tx, int ty, float s[4][4])
{
    #pragma unroll
    for (int i = 0; i < 4; ++i)
        #pragma unroll
        for (int u = 0; u < 4; ++u)
            s[i][u] = 0.0f;

    const float4* qp  = Qs + (4 * ty) * QPITCH;
    const int     xk  = tx & 7;
    const float4* kp0 = Ks + (tx     ) * 32;
    const float4* kp1 = Ks + (tx + 16) * 32;
    const float4* kp2 = Ks + (tx + 32) * 32;
    const float4* kp3 = Ks + (tx + 48) * 32;

    #pragma unroll 8
    for (int d4 = 0; d4 < 32; ++d4) {
        float4 q4[4], k4[4];
        q4[0] = qp[0 * QPITCH + d4];      // immediate-offset LDS, no ALU
        q4[1] = qp[1 * QPITCH + d4];
        q4[2] = qp[2 * QPITCH + d4];
        q4[3] = qp[3 * QPITCH + d4];
        const int kd = d4 ^ xk;           // one LOP3 shared by 4 K loads
        k4[0] = kp0[kd];
        k4[1] = kp1[kd];
        k4[2] = kp2[kd];
        k4[3] = kp3[kd];
        #pragma unroll
        for (int i = 0; i < 4; ++i)
            #pragma unroll
            for (int u = 0; u < 4; ++u) {
                s[i][u] = fmaf(q4[i].x, k4[u].x, s[i][u]);
                s[i][u] = fmaf(q4[i].y, k4[u].y, s[i][u]);
                s[i][u] = fmaf(q4[i].z, k4[u].z, s[i][u]);
                s[i][u] = fmaf(q4[i].w, k4[u].w, s[i][u]);
            }
    }
}

// Non-diagonal tiles: v = s*norm + am only (exact ref op order, no mask).
__device__ __forceinline__ void scale_add(float s[4][4], float v[4][4],
                                          const float* __restrict__ am,
                                          int kb, int tx, float norm)
{
    float amv[4];
    #pragma unroll
    for (int u = 0; u < 4; ++u) amv[u] = __ldg(&am[kb + tx + 16 * u]);

    #pragma unroll
    for (int i = 0; i < 4; ++i)
        #pragma unroll
        for (int u = 0; u < 4; ++u)
            v[i][u] = __fadd_rn(__fmul_rn(s[i][u], norm), amv[u]);
}

// Diagonal tile: same arithmetic + causal mask flags.
__device__ __forceinline__ void scale_mask(float s[4][4], float v[4][4], int dead[4][4],
                                           const float* __restrict__ am,
                                           int kb, int tx, int ty, int q0, float norm)
{
    float amv[4];
    #pragma unroll
    for (int u = 0; u < 4; ++u) amv[u] = __ldg(&am[kb + tx + 16 * u]);

    #pragma unroll
    for (int i = 0; i < 4; ++i) {
        const int qr = q0 + 4 * ty + i;
        #pragma unroll
        for (int u = 0; u < 4; ++u) {
            const int kc = kb + tx + 16 * u;
            v[i][u] = __fadd_rn(__fmul_rn(s[i][u], norm), amv[u]);
            dead[i][u] = kc > qr;
        }
    }
}

__global__ void __launch_bounds__(NT, 2)
attn_kernel(const float* __restrict__ Q, const float* __restrict__ K,
            const float* __restrict__ V, const float* __restrict__ AM,
            float* __restrict__ O)
{
    extern __shared__ float4 smem_raw[];
    Smem& sm = *reinterpret_cast<Smem*>(smem_raw);

    const int tid = threadIdx.x;
    const int tx  = tid & 15;        // 16 column-group lanes
    const int ty  = tid >> 4;        // 16 row groups of 4
    const int qt  = (int)gridDim.x - 1 - (int)blockIdx.x;  // heavy tiles first
    const int bh  = (int)blockIdx.y;
    const int b   = bh >> 5;
    const int h   = bh & 31;
    const int q0  = qt * TQ;

    // norm exactly as numpy computes it, rounding at every f32 step.
    const float sq128 = (float)11.313708498984761;   // f32(np.sqrt(128))
    const float norm  = __fmul_rn(__fmul_rn(__fdiv_rn(1.0f, sq128), 0.1f), 0.1f);
    const float c1    = (float)((1.0 / 255.0) * (1.0 / 10.0));

    const size_t base = (size_t)bh * SLEN * DHEAD;
    const float* am   = AM + (size_t)b * SLEN;
    const float4* gq  = reinterpret_cast<const float4*>(Q + base) + (size_t)q0 * (DHEAD / 4);
    const float4* gk0 = reinterpret_cast<const float4*>(K + base);
    const float4* gv0 = reinterpret_cast<const float4*>(V + base);

    // ---- load Q tile: coalesced, LINEAR pitch-33 store (conflict-free) ----
    #pragma unroll
    for (int j = 0; j < 8; ++j) {
        const int i = tid + NT * j;
        sm.Qs[(i >> 5) * QPITCH + (i & 31)] = gq[i];
    }

    // Per-thread partial stats (reduced across lanes once after pass 1).
    double Lp[4];
    float  mloc[4];
    #pragma unroll
    for (int i = 0; i < 4; ++i) { Lp[i] = 0.0; mloc[i] = -3.402823466e38f; }

    // ========== pass 1: K ping-pong, ONE barrier/tile, diag specialized ==========
    {
        float4* const buf[2] = { sm.KA, sm.KB };

        float4 pk[8];
        #pragma unroll
        for (int j = 0; j < 8; ++j) pk[j] = gk0[tid + NT * j];
        #pragma unroll
        for (int j = 0; j < 8; ++j) {
            const int i = tid + NT * j;
            const int r = i >> 5, d4 = i & 31;
            sm.KA[r * 32 + (d4 ^ (r & 7))] = pk[j];
        }
        __syncthreads();

        int p = 0;
        for (int kt = 0; kt < qt; ++kt) {        // NON-diagonal tiles only
            {   // prefetch next K tile (LDG hidden by GEMM)
                const float4* gk = gk0 + (size_t)(kt + 1) * TK * (DHEAD / 4);
                #pragma unroll
                for (int j = 0; j < 8; ++j) pk[j] = gk[tid + NT * j];
            }

            float s[4][4];
            gemm_qk(sm.Qs, buf[p], tx, ty, s);

            {   // stage next tile in the OTHER buffer (no race)
                float4* dst = buf[p ^ 1];
                #pragma unroll
                for (int j = 0; j < 8; ++j) {
                    const int i = tid + NT * j;
                    const int r = i >> 5, d4 = i & 31;
                    dst[r * 32 + (d4 ^ (r & 7))] = pk[j];
                }
            }

            float v[4][4];
            scale_add(s, v, am, kt * TK, tx, norm);

            #pragma unroll
            for (int i = 0; i < 4; ++i) {
                const float e0 = expP(v[i][0]);
                const float e1 = expP(v[i][1]);
                const float e2 = expP(v[i][2]);
                const float e3 = expP(v[i][3]);
                Lp[i] += (double)((e0 + e1) + (e2 + e3));
                mloc[i] = fmaxf(mloc[i],
                                fmaxf(fmaxf(v[i][0], v[i][1]),
                                      fmaxf(v[i][2], v[i][3])));
            }

            __syncthreads();     // publishes buf[p^1]
            p ^= 1;
        }

        // ---- diagonal tile (kt == qt), masked path ----
        {
            float s[4][4];
            gemm_qk(sm.Qs, buf[p], tx, ty, s);
            float v[4][4]; int dead[4][4];
            scale_mask(s, v, dead, am, qt * TK, tx, ty, q0, norm);

            #pragma unroll
            for (int i = 0; i < 4; ++i) {
                const float e0 = dead[i][0] ? 0.0f : expP(v[i][0]);
                const float e1 = dead[i][1] ? 0.0f : expP(v[i][1]);
                const float e2 = dead[i][2] ? 0.0f : expP(v[i][2]);
                const float e3 = dead[i][3] ? 0.0f : expP(v[i][3]);
                Lp[i] += (double)((e0 + e1) + (e2 + e3));

                const float t0 = dead[i][0] ? -3.402823466e38f : v[i][0];
                const float t1 = dead[i][1] ? -3.402823466e38f : v[i][1];
                const float t2 = dead[i][2] ? -3.402823466e38f : v[i][2];
                const float t3 = dead[i][3] ? -3.402823466e38f : v[i][3];
                mloc[i] = fmaxf(mloc[i], fmaxf(fmaxf(t0, t1), fmaxf(t2, t3)));
            }
        }
    }

    // ---- one-time cross-lane reduction (16 tx lanes in each half-warp) ----
    double L[4];
    float  m[4];
    #pragma unroll
    for (int i = 0; i < 4; ++i) {
        float t = mloc[i];
        #pragma unroll
        for (int msk = 1; msk < 16; msk <<= 1)
            t = fmaxf(t, __shfl_xor_sync(0xffffffffu, t, msk));
        m[i] = t;                                   // exact f32 row max

        double rs = Lp[i];
        #pragma unroll
        for (int msk = 1; msk < 16; msk <<= 1)
            rs += __shfl_xor_sync(0xffffffffu, rs, msk);
        L[i] = rs;
    }

    // ---- l in f32 (value the ref divides by): l = L * exp(-m), near-exact ----
    float lf[4];
    int needp = 0;
    #pragma unroll
    for (int i = 0; i < 4; ++i) {
        lf[i] = (float)(L[i] * exp(-(double)m[i]));
        // skip test with EXACTLY the pass-2 weight arithmetic at e = 1
        // (argmax element has e = expCR(0) = 1); weights monotone in e.
        const float zmax = __fmul_rn(__fdiv_rn(1.0f, lf[i]), 255.0f);
        if (rintf(zmax) >= 1.0f) needp = 1;
    }
    const int need = __syncthreads_or(needp);

    if (!need) {
        // whole tile quantizes to zero — write zeros (out is poisoned)
        const float4 z = make_float4(0.f, 0.f, 0.f, 0.f);
        #pragma unroll
        for (int i = 0; i < 4; ++i) {
            const int row = q0 + 4 * ty + i;
            float4* p = reinterpret_cast<float4*>(
                O + ((size_t)b * SLEN + row) * (HEADS * DHEAD) + h * DHEAD + 8 * tx);
            p[0] = z; p[1] = z;
        }
        return;
    }

    // ================= pass 2: quantized weights + W @ V =================
    // fp32 accumulators, fmaf in STRICTLY ascending global k order
    // (Eigen-sequential emulation; zero weights add exactly 0).
    float acc[4][8];
    #pragma unroll
    for (int i = 0; i < 4; ++i)
        #pragma unroll
        for (int jj = 0; jj < 8; ++jj) acc[i][jj] = 0.0f;

    for (int kt = 0; kt <= qt; ++kt) {
        __syncthreads();   // previous iteration's KB/Wu readers done
        {
            const float4* gk = gk0 + (size_t)kt * TK * (DHEAD / 4);
            const float4* gv = gv0 + (size_t)kt * TK * (DHEAD / 4);
            #pragma unroll
            for (int j = 0; j < 8; ++j) {
                const int i = tid + NT * j;
                const int r = i >> 5, d4 = i & 31;
                const int idx = r * 32 + (d4 ^ (r & 7));
                sm.KA[idx] = gk[i];
                sm.KB[idx] = gv[i];    // V tile
            }
        }
        __syncthreads();

        float s[4][4];
        gemm_qk(sm.Qs, sm.KA, tx, ty, s);                  // identical to pass 1
        float v[4][4];
        const bool diag = (kt == qt);

        if (!diag) {
            scale_add(s, v, am, kt * TK, tx, norm);
            // w = clip(rint(f32(f32(expCR(f32(v-m)) / l) * 255)), 0, 255)
            #pragma unroll
            for (int u = 0; u < 4; ++u) {
                const int c = tx + 16 * u;
                unsigned pw = 0;
                #pragma unroll
                for (int i = 0; i < 4; ++i) {
                    const float t2 = __fadd_rn(v[i][u], -m[i]);  // f32 (s - max)
                    const float e  = expCR(t2);                  // = 1.0f at argmax
                    const float z  = __fmul_rn(__fdiv_rn(e, lf[i]), 255.0f);
                    const float w  = fminf(rintf(z), 255.0f);    // integer in [0,255]
                    pw |= ((unsigned)w) << (8 * i);
                }
                sm.Wu[c * 18 + ty] = pw;
            }
        } else {
            int dead[4][4];
            scale_mask(s, v, dead, am, kt * TK, tx, ty, q0, norm);
            #pragma unroll
            for (int u = 0; u < 4; ++u) {
                const int c = tx + 16 * u;
                unsigned pw = 0;
                #pragma unroll
                for (int i = 0; i < 4; ++i) {
                    float w;
                    if (dead[i][u]) {
                        w = 0.0f;
                    } else {
                        const float t2 = __fadd_rn(v[i][u], -m[i]);
                        const float e  = expCR(t2);
                        const float z  = __fmul_rn(__fdiv_rn(e, lf[i]), 255.0f);
                        w = fminf(rintf(z), 255.0f);
                    }
                    pw |= ((unsigned)w) << (8 * i);
                }
                sm.Wu[c * 18 + ty] = pw;
            }
        }
        __syncthreads();

        // acc[r][d] += W[r][c] * V[c][d], c ascending (global k ascending).
        // Weights are exact small integers: u8 -> f32 conversion is exact.
        #pragma unroll 8
        for (int c = 0; c < 64; ++c) {
            const unsigned pw = sm.Wu[c * 18 + ty];
            const float4 v0 = sm.KB[c * 32 + ((2 * tx)     ^ (c & 7))];
            const float4 v1 = sm.KB[c * 32 + ((2 * tx + 1) ^ (c & 7))];
            float wv[4];
            wv[0] = (float)(int)__byte_perm(pw, 0, 0x4440);
            wv[1] = (float)(int)__byte_perm(pw, 0, 0x4441);
            wv[2] = (float)(int)__byte_perm(pw, 0, 0x4442);
            wv[3] = (float)(int)__byte_perm(pw, 0, 0x4443);
            #pragma unroll
            for (int i = 0; i < 4; ++i) {
                acc[i][0] = fmaf(wv[i], v0.x, acc[i][0]);
                acc[i][1] = fmaf(wv[i], v0.y, acc[i][1]);
                acc[i][2] = fmaf(wv[i], v0.z, acc[i][2]);
                acc[i][3] = fmaf(wv[i], v0.w, acc[i][3]);
                acc[i][4] = fmaf(wv[i], v1.x, acc[i][4]);
                acc[i][5] = fmaf(wv[i], v1.y, acc[i][5]);
                acc[i][6] = fmaf(wv[i], v1.z, acc[i][6]);
                acc[i][7] = fmaf(wv[i], v1.w, acc[i][7]);
            }
        }
    }

    // ---- epilogue: exact ref op order on the emulated f32 einsum result ----
    #pragma unroll
    for (int i = 0; i < 4; ++i) {
        float o[8];
        #pragma unroll
        for (int jj = 0; jj < 8; ++jj) {
            float y = __fmul_rn(acc[i][jj], c1);   // out * f32(1/2550)
            y = __fmul_rn(y, 127.0f);              // * REQUANT
            y = rintf(y);                          // round half-to-even
            o[jj] = fminf(fmaxf(y, -128.0f), 127.0f);
        }
        const int row = q0 + 4 * ty + i;
        float4* p = reinterpret_cast<float4*>(
            O + ((size_t)b * SLEN + row) * (HEADS * DHEAD) + h * DHEAD + 8 * tx);
        p[0] = make_float4(o[0], o[1], o[2], o[3]);
        p[1] = make_float4(o[4], o[5], o[6], o[7]);
    }
}

extern "C" void kernel_launch(void* const* d_in, const int* in_sizes, int n_in,
                              void* d_out, int out_size)
{
    (void)in_sizes; (void)n_in; (void)out_size;
    const float* q  = (const float*)d_in[0];
    const float* k  = (const float*)d_in[1];
    const float* v  = (const float*)d_in[2];
    const float* am = (const float*)d_in[3];
    float* out = (float*)d_out;

    const int smem = (int)sizeof(Smem);   // 103936 B -> 2 CTAs/SM with slack
    cudaFuncSetAttribute(attn_kernel, cudaFuncAttributeMaxDynamicSharedMemorySize, smem);

    dim3 grid(SLEN / TQ, 2 * HEADS);      // (32 q-tiles, 64 batch*head)
    attn_kernel<<<grid, NT, smem>>>(q, k, v, am, out);
}